// round 1
// baseline (speedup 1.0000x reference)
#include <cuda_runtime.h>
#include <math.h>

// Problem constants
#define NTOK 16384   // B*N tokens
#define DD   1024    // model dim
#define CC   256     // E*S slots
#define BATCH 64
#define NSEQ 256
#define NEXP 16
#define HH   256

// ---------------- scratch (static device globals; no allocs allowed) --------
__device__ float g_xn[NTOK * DD];        // LayerNorm output          (64 MB)
__device__ float g_rnorm[NTOK];          // 1/max(||xn||,eps) per token
__device__ float g_cinv[CC];             // 1/max(||mu[:,c]||,eps)
__device__ float g_logits[NTOK * CC];    // cosine logits             (16 MB)
__device__ float g_dispatch[NTOK * CC];  // softmax over tokens       (16 MB)
__device__ float g_combine[NTOK * CC];   // softmax over slots        (16 MB)
__device__ float g_slot[BATCH * CC * DD];// slot_in, then slot_out    (64 MB)
__device__ float g_h[NEXP * 1024 * HH];  // expert hidden             (16 MB)

// ---------------- LayerNorm + token L2 norm ---------------------------------
__global__ void ln_kernel(const float* __restrict__ x,
                          const float* __restrict__ gamma,
                          const float* __restrict__ beta) {
    int t = blockIdx.x;
    int tid = threadIdx.x;
    const float* xr = x + (size_t)t * DD;
    float* yr = g_xn + (size_t)t * DD;

    float lv[4];
    float s = 0.f, ss = 0.f;
#pragma unroll
    for (int j = 0; j < 4; j++) {
        float a = xr[tid + 256 * j];
        lv[j] = a; s += a; ss += a * a;
    }
    __shared__ float r1[256], r2[256];
    r1[tid] = s; r2[tid] = ss; __syncthreads();
    for (int o = 128; o > 0; o >>= 1) {
        if (tid < o) { r1[tid] += r1[tid + o]; r2[tid] += r2[tid + o]; }
        __syncthreads();
    }
    float mean = r1[0] * (1.f / DD);
    float var  = r2[0] * (1.f / DD) - mean * mean;
    float rstd = rsqrtf(var + 1e-5f);

    float s2 = 0.f;
#pragma unroll
    for (int j = 0; j < 4; j++) {
        int i = tid + 256 * j;
        float y = (lv[j] - mean) * rstd * gamma[i] + beta[i];
        yr[i] = y; s2 += y * y;
    }
    __syncthreads();
    r1[tid] = s2; __syncthreads();
    for (int o = 128; o > 0; o >>= 1) {
        if (tid < o) r1[tid] += r1[tid + o];
        __syncthreads();
    }
    if (tid == 0) {
        float n = sqrtf(r1[0]);
        g_rnorm[t] = 1.f / fmaxf(n, 1e-12f);
    }
}

// ---------------- mu column norms (over D, per slot column) -----------------
__global__ void munorm_kernel(const float* __restrict__ mu) {
    int c = blockIdx.x, tid = threadIdx.x;
    float s = 0.f;
    for (int d = tid; d < DD; d += 256) {
        float a = mu[(size_t)d * CC + c];
        s += a * a;
    }
    __shared__ float r[256];
    r[tid] = s; __syncthreads();
    for (int o = 128; o > 0; o >>= 1) {
        if (tid < o) r[tid] += r[tid + o];
        __syncthreads();
    }
    if (tid == 0) g_cinv[c] = 1.f / fmaxf(sqrtf(r[0]), 1e-12f);
}

// ---------------- combine: row softmax over 256 slots (warp per row) --------
__global__ void combine_kernel() {
    int row = blockIdx.x * 8 + threadIdx.y;
    int lane = threadIdx.x;
    const float* lr = g_logits + (size_t)row * CC;
    float v[8]; float mx = -1e30f;
#pragma unroll
    for (int j = 0; j < 8; j++) { v[j] = lr[lane + 32 * j]; mx = fmaxf(mx, v[j]); }
    for (int o = 16; o > 0; o >>= 1) mx = fmaxf(mx, __shfl_xor_sync(0xffffffffu, mx, o));
    float s = 0.f;
#pragma unroll
    for (int j = 0; j < 8; j++) { v[j] = __expf(v[j] - mx); s += v[j]; }
    for (int o = 16; o > 0; o >>= 1) s += __shfl_xor_sync(0xffffffffu, s, o);
    float inv = 1.f / s;
    float* cr = g_combine + (size_t)row * CC;
#pragma unroll
    for (int j = 0; j < 8; j++) cr[lane + 32 * j] = v[j] * inv;
}

// ---------------- dispatch: softmax over tokens n per (b, slot) -------------
// Block = (slot-tile of 32 columns, batch). SMEM-transposed tile keeps global
// loads coalesced; column reductions are conflict-free (row stride 32 floats).
__global__ void dispatch_kernel() {
    int b = blockIdx.y;
    int c0 = blockIdx.x * 32;
    int tid = threadIdx.x;
    int c = tid & 31, nb = tid >> 5;

    __shared__ float tile[256][32];
    __shared__ float pred[8][32];
    __shared__ float colv[32];

    const size_t base = ((size_t)b * NSEQ) * CC + c0;
#pragma unroll
    for (int it = 0; it < 32; it++) {
        int n = nb + 8 * it;
        tile[n][c] = g_logits[base + (size_t)n * CC + c];
    }
    __syncthreads();

    float mx = -1e30f;
#pragma unroll
    for (int j = 0; j < 32; j++) mx = fmaxf(mx, tile[nb * 32 + j][c]);
    pred[nb][c] = mx; __syncthreads();
    if (nb == 0) {
        float m = pred[0][c];
#pragma unroll
        for (int j = 1; j < 8; j++) m = fmaxf(m, pred[j][c]);
        colv[c] = m;
    }
    __syncthreads();
    float cm = colv[c];

    float s = 0.f;
#pragma unroll
    for (int j = 0; j < 32; j++) {
        float e = __expf(tile[nb * 32 + j][c] - cm);
        tile[nb * 32 + j][c] = e; s += e;
    }
    pred[nb][c] = s; __syncthreads();
    if (nb == 0) {
        float t = 0.f;
#pragma unroll
        for (int j = 0; j < 8; j++) t += pred[j][c];
        colv[c] = 1.f / t;
    }
    __syncthreads();
    float inv = colv[c];
#pragma unroll
    for (int it = 0; it < 32; it++) {
        int n = nb + 8 * it;
        g_dispatch[base + (size_t)n * CC + c] = tile[n][c] * inv;
    }
}

// ---------------- generic 64x64x16 fp32 SGEMM, 5 fused variants -------------
// MODE 0: logits  = xn[16384,1024] @ mu[1024,256], * scale*rnorm[row]*cinv[col]
// MODE 1: slot_in[b] = dispatch[b]^T[256,256] @ xn[b][256,1024]     (TN, batched)
// MODE 2: h[e]    = gather(slot_in)[1024,1024] @ w1[e][1024,256], GELU(+b1)
// MODE 3: slot_out= h[e][1024,256] @ w2[e][256,1024], +b2, scatter rows
// MODE 4: out[b]  = combine[b][256,256] @ slot_out[b][256,1024]
template <int MODE>
__global__ void __launch_bounds__(256) gemm_k(const float* __restrict__ X1,
                                              const float* __restrict__ X2,
                                              float* __restrict__ Cout,
                                              const float* __restrict__ sp) {
    constexpr int Nx = (MODE == 0 || MODE == 2) ? 256 : 1024;
    constexpr int Kx = (MODE == 0 || MODE == 2) ? 1024 : 256;

    const int z = blockIdx.z;
    const int m0 = blockIdx.y * 64;
    const int n0 = blockIdx.x * 64;
    const int tid = threadIdx.x;
    const int tx = tid & 15, ty = tid >> 4;

    const float* Ap; const float* Bp;
    if (MODE == 0)      { Ap = g_xn;                                  Bp = X1; }
    else if (MODE == 1) { Ap = g_dispatch + (size_t)z * NSEQ * CC;    Bp = g_xn + (size_t)z * NSEQ * DD; }
    else if (MODE == 2) { Ap = g_slot;                                Bp = X1 + (size_t)z * DD * HH; }
    else if (MODE == 3) { Ap = g_h + (size_t)z * 1024 * HH;           Bp = X1 + (size_t)z * HH * DD; }
    else                { Ap = g_combine + (size_t)z * NSEQ * CC;     Bp = g_slot + (size_t)z * CC * DD; }

    __shared__ float As[16][64];
    __shared__ float Bs[16][68];

    float acc[4][4] = {};

    for (int k0 = 0; k0 < Kx; k0 += 16) {
        // ---- load A tile into As[k][m] (k-major) ----
        if (MODE == 1) {
            // A is [K=256, M=256] row-major (dispatch layout [n, c])
            int k = tid >> 4, mq = (tid & 15) << 2;
            float4 av = *reinterpret_cast<const float4*>(&Ap[(size_t)(k0 + k) * 256 + m0 + mq]);
            *reinterpret_cast<float4*>(&As[k][mq]) = av;
        } else {
            int m = tid >> 2, kq = (tid & 3) << 2;
            const float* arow;
            if (MODE == 2) {
                int g = m0 + m;                        // g = b*16 + s
                int r = (g >> 4) * CC + z * 16 + (g & 15);
                arow = &Ap[(size_t)r * DD];
            } else {
                arow = &Ap[(size_t)(m0 + m) * Kx];
            }
            float4 av = *reinterpret_cast<const float4*>(&arow[k0 + kq]);
            As[kq + 0][m] = av.x; As[kq + 1][m] = av.y;
            As[kq + 2][m] = av.z; As[kq + 3][m] = av.w;
        }
        // ---- load B tile ----
        {
            int k = tid >> 4, nq = (tid & 15) << 2;
            float4 bv = *reinterpret_cast<const float4*>(&Bp[(size_t)(k0 + k) * Nx + n0 + nq]);
            *reinterpret_cast<float4*>(&Bs[k][nq]) = bv;
        }
        __syncthreads();

#pragma unroll
        for (int k = 0; k < 16; k++) {
            float4 a = *reinterpret_cast<const float4*>(&As[k][ty << 2]);
            float4 b = *reinterpret_cast<const float4*>(&Bs[k][tx << 2]);
            float av4[4] = {a.x, a.y, a.z, a.w};
            float bv4[4] = {b.x, b.y, b.z, b.w};
#pragma unroll
            for (int i = 0; i < 4; i++)
#pragma unroll
                for (int j = 0; j < 4; j++)
                    acc[i][j] += av4[i] * bv4[j];
        }
        __syncthreads();
    }

    // ---- epilogue ----
#pragma unroll
    for (int i = 0; i < 4; i++) {
        int row = m0 + (ty << 2) + i;
#pragma unroll
        for (int j = 0; j < 4; j++) {
            int col = n0 + (tx << 2) + j;
            float v = acc[i][j];
            if (MODE == 0) {
                v *= sp[0] * g_rnorm[row] * g_cinv[col];
                g_logits[(size_t)row * CC + col] = v;
            } else if (MODE == 1) {
                g_slot[((size_t)z * CC + row) * DD + col] = v;
            } else if (MODE == 2) {
                v += X2[z * HH + col];
                v = 0.5f * v * (1.f + erff(v * 0.70710678118654752f));
                g_h[((size_t)z * 1024 + row) * HH + col] = v;
            } else if (MODE == 3) {
                v += X2[z * DD + col];
                int r = (row >> 4) * CC + z * 16 + (row & 15);
                g_slot[(size_t)r * DD + col] = v;
            } else {
                Cout[((size_t)z * NSEQ + row) * DD + col] = v;
            }
        }
    }
}

// ---------------- launch ----------------------------------------------------
extern "C" void kernel_launch(void* const* d_in, const int* in_sizes, int n_in,
                              void* d_out, int out_size) {
    const float* x     = (const float*)d_in[0];
    const float* gamma = (const float*)d_in[1];
    const float* beta  = (const float*)d_in[2];
    const float* mu    = (const float*)d_in[3];
    const float* scale = (const float*)d_in[4];
    const float* w1    = (const float*)d_in[5];
    const float* b1    = (const float*)d_in[6];
    const float* w2    = (const float*)d_in[7];
    const float* b2    = (const float*)d_in[8];
    float* out = (float*)d_out;

    ln_kernel<<<NTOK, 256>>>(x, gamma, beta);
    munorm_kernel<<<CC, 256>>>(mu);
    // logits = xn_unit * scale @ mu_unit   (norms folded into epilogue)
    gemm_k<0><<<dim3(4, 256, 1), 256>>>(mu, nullptr, nullptr, scale);
    combine_kernel<<<NTOK / 8, dim3(32, 8)>>>();
    dispatch_kernel<<<dim3(8, 64), 256>>>();
    // slot_in[b] = dispatch[b]^T @ xn[b]
    gemm_k<1><<<dim3(16, 4, 64), 256>>>(nullptr, nullptr, nullptr, nullptr);
    // h[e] = gelu(slot_in rows @ w1[e] + b1[e])
    gemm_k<2><<<dim3(4, 16, 16), 256>>>(w1, b1, nullptr, nullptr);
    // slot_out = h[e] @ w2[e] + b2[e]   (scatter back into g_slot)
    gemm_k<3><<<dim3(16, 16, 16), 256>>>(w2, b2, nullptr, nullptr);
    // out[b] = combine[b] @ slot_out[b]
    gemm_k<4><<<dim3(16, 4, 64), 256>>>(nullptr, nullptr, out, nullptr);
}

// round 3
// speedup vs baseline: 2.8979x; 2.8979x over previous
#include <cuda_runtime.h>
#include <math.h>
#include <stdint.h>

#define NTOK 16384
#define DD   1024
#define CC   256
#define BATCH 64
#define NSEQ 256
#define NEXP 16
#define HH   256

// ---------------- scratch ----------------------------------------------------
__device__ float g_xn[NTOK * DD];
__device__ float g_rnorm[NTOK];
__device__ float g_cinv[CC];
__device__ float g_logits[NTOK * CC];
__device__ float g_dispT[BATCH * CC * NSEQ];   // [b][c][n]
__device__ float g_combine[NTOK * CC];
__device__ float g_slot[BATCH * CC * DD];      // slot_in then slot_out
__device__ float g_h[NEXP * 1024 * HH];

// ---------------- helpers ----------------------------------------------------
__device__ __forceinline__ float tf32r(float x) {
    asm("cvt.rna.tf32.f32 %0, %0;" : "+f"(x));
    return x;
}
__device__ __forceinline__ void mma_tf32(float* d, const uint32_t* a, const uint32_t* b) {
    asm volatile(
        "mma.sync.aligned.m16n8k8.row.col.f32.tf32.tf32.f32 "
        "{%0,%1,%2,%3}, {%4,%5,%6,%7}, {%8,%9}, {%0,%1,%2,%3};"
        : "+f"(d[0]), "+f"(d[1]), "+f"(d[2]), "+f"(d[3])
        : "r"(a[0]), "r"(a[1]), "r"(a[2]), "r"(a[3]), "r"(b[0]), "r"(b[1]));
}
// bank-dispersal xor for smem tiles with 8-word rows
__device__ __forceinline__ int xmap(int i) {
    return (4 * ((i >> 2) & 1)) ^ ((i >> 3) & 3);
}

// ---------------- LayerNorm + token L2 norm ----------------------------------
__global__ void ln_kernel(const float* __restrict__ x,
                          const float* __restrict__ gamma,
                          const float* __restrict__ beta) {
    int t = blockIdx.x, tid = threadIdx.x;
    const float* xr = x + (size_t)t * DD;
    float* yr = g_xn + (size_t)t * DD;
    float lv[4], s = 0.f, ss = 0.f;
#pragma unroll
    for (int j = 0; j < 4; j++) {
        float a = xr[tid + 256 * j];
        lv[j] = a; s += a; ss += a * a;
    }
    __shared__ float r1[256], r2[256];
    r1[tid] = s; r2[tid] = ss; __syncthreads();
    for (int o = 128; o > 0; o >>= 1) {
        if (tid < o) { r1[tid] += r1[tid + o]; r2[tid] += r2[tid + o]; }
        __syncthreads();
    }
    float mean = r1[0] * (1.f / DD);
    float var  = r2[0] * (1.f / DD) - mean * mean;
    float rstd = rsqrtf(var + 1e-5f);
    float s2 = 0.f;
#pragma unroll
    for (int j = 0; j < 4; j++) {
        int i = tid + 256 * j;
        float y = (lv[j] - mean) * rstd * gamma[i] + beta[i];
        yr[i] = y; s2 += y * y;
    }
    __syncthreads();
    r1[tid] = s2; __syncthreads();
    for (int o = 128; o > 0; o >>= 1) {
        if (tid < o) r1[tid] += r1[tid + o];
        __syncthreads();
    }
    if (tid == 0) g_rnorm[t] = 1.f / fmaxf(sqrtf(r1[0]), 1e-12f);
}

__global__ void munorm_kernel(const float* __restrict__ mu) {
    int c = blockIdx.x, tid = threadIdx.x;
    float s = 0.f;
    for (int d = tid; d < DD; d += 256) {
        float a = mu[(size_t)d * CC + c];
        s += a * a;
    }
    __shared__ float r[256];
    r[tid] = s; __syncthreads();
    for (int o = 128; o > 0; o >>= 1) {
        if (tid < o) r[tid] += r[tid + o];
        __syncthreads();
    }
    if (tid == 0) g_cinv[c] = 1.f / fmaxf(sqrtf(r[0]), 1e-12f);
}

// ---------------- combine softmax --------------------------------------------
__global__ void combine_kernel() {
    int row = blockIdx.x * 8 + threadIdx.y;
    int lane = threadIdx.x;
    const float* lr = g_logits + (size_t)row * CC;
    float v[8]; float mx = -1e30f;
#pragma unroll
    for (int j = 0; j < 8; j++) { v[j] = lr[lane + 32 * j]; mx = fmaxf(mx, v[j]); }
    for (int o = 16; o > 0; o >>= 1) mx = fmaxf(mx, __shfl_xor_sync(0xffffffffu, mx, o));
    float s = 0.f;
#pragma unroll
    for (int j = 0; j < 8; j++) { v[j] = __expf(v[j] - mx); s += v[j]; }
    for (int o = 16; o > 0; o >>= 1) s += __shfl_xor_sync(0xffffffffu, s, o);
    float inv = 1.f / s;
    float* cr = g_combine + (size_t)row * CC;
#pragma unroll
    for (int j = 0; j < 8; j++) cr[lane + 32 * j] = v[j] * inv;
}

// ---------------- dispatch softmax over tokens; transposed output -------------
__global__ void dispatch_kernel() {
    int b = blockIdx.y, c0 = blockIdx.x * 32, tid = threadIdx.x;
    int c = tid & 31, nb = tid >> 5;
    __shared__ float tile[256][33];
    __shared__ float pred[8][32];
    __shared__ float colv[32];

    const size_t base = ((size_t)b * NSEQ) * CC + c0;
#pragma unroll
    for (int it = 0; it < 32; it++) {
        int n = nb + 8 * it;
        tile[n][c] = g_logits[base + (size_t)n * CC + c];
    }
    __syncthreads();
    float mx = -1e30f;
#pragma unroll
    for (int j = 0; j < 32; j++) mx = fmaxf(mx, tile[nb * 32 + j][c]);
    pred[nb][c] = mx; __syncthreads();
    if (nb == 0) {
        float m = pred[0][c];
#pragma unroll
        for (int j = 1; j < 8; j++) m = fmaxf(m, pred[j][c]);
        colv[c] = m;
    }
    __syncthreads();
    float cm = colv[c];
    float s = 0.f;
#pragma unroll
    for (int j = 0; j < 32; j++) {
        float e = __expf(tile[nb * 32 + j][c] - cm);
        tile[nb * 32 + j][c] = e; s += e;
    }
    pred[nb][c] = s; __syncthreads();
    if (nb == 0) {
        float t = 0.f;
#pragma unroll
        for (int j = 0; j < 8; j++) t += pred[j][c];
        colv[c] = 1.f / t;
    }
    __syncthreads();
    int lane2 = tid & 31, cg = tid >> 5;
#pragma unroll
    for (int cc2 = 0; cc2 < 4; cc2++) {
        int cl = cg + 8 * cc2;
        float inv = colv[cl];
        size_t ob = ((size_t)b * CC + c0 + cl) * NSEQ;
#pragma unroll
        for (int itn = 0; itn < 8; itn++) {
            int n = lane2 + 32 * itn;
            g_dispT[ob + n] = tile[n][cl] * inv;
        }
    }
}

// ---------------- tf32 mma.sync GEMM: CTA 128Mx256N, warp 64x64 ---------------
// MODE 0: logits  = xn @ mu            (M=16384,K=1024,N=256)  + cosine scale
// MODE 1: slot_in = dispT[b] @ xn[b]   (M=256,  K=256, N=1024)
// MODE 2: h       = gather(slot) @ w1  (M=1024, K=1024,N=256)  + bias + GELU
// MODE 3: slot_out= h[e] @ w2[e]       (M=1024, K=256, N=1024) + bias + scatter
// MODE 4: out[b]  = combine[b] @ slot  (M=256,  K=256, N=1024)
template <int MODE>
__global__ void __launch_bounds__(256) gemm_mma(const float* __restrict__ X1,
                                                const float* __restrict__ X2,
                                                float* __restrict__ Cout,
                                                const float* __restrict__ sp) {
    constexpr int Kx  = (MODE == 0 || MODE == 2) ? 1024 : 256;
    constexpr int ldb = (MODE == 0 || MODE == 2) ? 256 : 1024;
    constexpr int lda = (MODE == 0 || MODE == 2) ? 1024 : 256;
    constexpr int NC  = Kx / 32;

    extern __shared__ float sm[];   // 2 stages x (A 4096 + B 8192) floats
    const int tid = threadIdx.x, wid = tid >> 5, lane = tid & 31;
    const int warp_m = wid & 1, warp_n = wid >> 1;
    const int r = lane >> 2, t = lane & 3;
    const int z = blockIdx.z, m0 = blockIdx.y * 128, n0 = blockIdx.x * 256;

    const float* Abase;
    const float* Bbase;
    if (MODE == 0)      { Abase = g_xn + (size_t)m0 * 1024;                         Bbase = X1; }
    else if (MODE == 1) { Abase = g_dispT + ((size_t)z << 16) + (size_t)m0 * 256;   Bbase = g_xn + ((size_t)z << 18); }
    else if (MODE == 2) { Abase = g_slot;                                           Bbase = X1 + ((size_t)z << 18); }
    else if (MODE == 3) { Abase = g_h + ((size_t)z << 18) + (size_t)m0 * 256;       Bbase = X1 + ((size_t)z << 18); }
    else                { Abase = g_combine + ((size_t)z << 16) + (size_t)m0 * 256; Bbase = g_slot + ((size_t)z << 18); }

    // per-thread staging geometry
    const int sm_a = tid >> 3;        // A row handled (4 rows: sm_a per i? see loop)
    const int sk4  = tid & 7;         // float4 index along k
    const int bn   = tid;             // B column handled (0..255)
    const int xb_n = xmap(bn);
    const float* bcol = Bbase + n0 + bn;

    // A row pointers for the 4 staging iterations (m = (tid>>3) + 32*i)
    const float* arow_i[4];
#pragma unroll
    for (int i = 0; i < 4; i++) {
        int m = sm_a + 32 * i;
        if (MODE == 2) {
            int g = m0 + m;
            arow_i[i] = g_slot + (size_t)(((g >> 4) << 8) + (z << 4) + (g & 15)) * 1024;
        } else {
            arow_i[i] = Abase + (size_t)m * lda;
        }
    }

    // fragment smem word offsets (constant across chunks)
    int aw[4][2], bw[8];
#pragma unroll
    for (int mt = 0; mt < 4; mt++) {
        int mr0 = warp_m * 64 + mt * 16 + r;
        aw[mt][0] = mr0 * 8 + (t ^ xmap(mr0));
        aw[mt][1] = (mr0 + 8) * 8 + (t ^ xmap(mr0 + 8));
    }
#pragma unroll
    for (int nt = 0; nt < 8; nt++) {
        int nn = warp_n * 64 + nt * 8 + r;
        bw[nt] = nn * 8 + (t ^ xmap(nn));
    }

    float acc[4][8][4];
#pragma unroll
    for (int mt = 0; mt < 4; mt++)
#pragma unroll
        for (int nt = 0; nt < 8; nt++)
#pragma unroll
            for (int q = 0; q < 4; q++) acc[mt][nt][q] = 0.f;

    float4 pa[4];
    float  pb[32];

    // ---- prologue: load + store chunk 0
#pragma unroll
    for (int i = 0; i < 4; i++)
        pa[i] = *(const float4*)(arow_i[i] + sk4 * 4);
#pragma unroll
    for (int k = 0; k < 32; k++)
        pb[k] = bcol[(size_t)k * ldb];

    int buf = 0;
#pragma unroll 1
    for (int c = 0; c < NC; c++) {
        // store prefetched chunk c into buf
        {
            float* As = sm + buf * 12288;
            float* Bs = As + 4096;
#pragma unroll
            for (int i = 0; i < 4; i++) {
                int m = sm_a + 32 * i;
                int xa = xmap(m);
                float vv[4] = { tf32r(pa[i].x), tf32r(pa[i].y), tf32r(pa[i].z), tf32r(pa[i].w) };
#pragma unroll
                for (int e = 0; e < 4; e++) {
                    int k = sk4 * 4 + e;
                    As[(k >> 3) * 1024 + m * 8 + ((k & 7) ^ xa)] = vv[e];
                }
            }
#pragma unroll
            for (int k = 0; k < 32; k++)
                Bs[(k >> 3) * 2048 + bn * 8 + ((k & 7) ^ xb_n)] = tf32r(pb[k]);
        }
        __syncthreads();

        // prefetch chunk c+1 (LDG only; STS happens next iteration)
        if (c + 1 < NC) {
            int k0 = (c + 1) * 32;
#pragma unroll
            for (int i = 0; i < 4; i++)
                pa[i] = *(const float4*)(arow_i[i] + k0 + sk4 * 4);
#pragma unroll
            for (int k = 0; k < 32; k++)
                pb[k] = bcol[(size_t)(k0 + k) * ldb];
        }

        // compute on buf
        {
            const uint32_t* As = (const uint32_t*)(sm + buf * 12288);
            const uint32_t* Bs = As + 4096;
#pragma unroll
            for (int k8 = 0; k8 < 4; k8++) {
                const uint32_t* A8 = As + k8 * 1024;
                const uint32_t* B8 = Bs + k8 * 2048;
                uint32_t a[4][4], b[8][2];
#pragma unroll
                for (int mt = 0; mt < 4; mt++) {
                    a[mt][0] = A8[aw[mt][0]];
                    a[mt][1] = A8[aw[mt][1]];
                    a[mt][2] = A8[aw[mt][0] ^ 4];
                    a[mt][3] = A8[aw[mt][1] ^ 4];
                }
#pragma unroll
                for (int nt = 0; nt < 8; nt++) {
                    b[nt][0] = B8[bw[nt]];
                    b[nt][1] = B8[bw[nt] ^ 4];
                }
#pragma unroll
                for (int mt = 0; mt < 4; mt++)
#pragma unroll
                    for (int nt = 0; nt < 8; nt++)
                        mma_tf32(acc[mt][nt], a[mt], b[nt]);
            }
        }
        __syncthreads();
        buf ^= 1;
    }

    // ---- epilogue
    float spv = (MODE == 0) ? sp[0] : 0.f;
#pragma unroll
    for (int mt = 0; mt < 4; mt++) {
        int row = m0 + warp_m * 64 + mt * 16 + r;
#pragma unroll
        for (int half = 0; half < 2; half++) {
            int rw = row + half * 8;
            float rs0 = 0.f;
            if (MODE == 0) rs0 = spv * g_rnorm[rw];
            float* orow;
            if (MODE == 0)      orow = g_logits + (size_t)rw * 256;
            else if (MODE == 1) orow = g_slot + (((size_t)z << 8) + rw) * 1024;
            else if (MODE == 2) orow = g_h + (((size_t)z << 10) + rw) * 256;
            else if (MODE == 3) {
                int rr = ((rw >> 4) << 8) + (z << 4) + (rw & 15);
                orow = g_slot + (size_t)rr * 1024;
            } else              orow = Cout + (((size_t)z << 8) + rw) * 1024;
#pragma unroll
            for (int nt = 0; nt < 8; nt++) {
                int col = n0 + warp_n * 64 + nt * 8 + 2 * t;
                float v0 = acc[mt][nt][half * 2 + 0];
                float v1 = acc[mt][nt][half * 2 + 1];
                if (MODE == 0) {
                    v0 *= rs0 * g_cinv[col];
                    v1 *= rs0 * g_cinv[col + 1];
                } else if (MODE == 2) {
                    v0 += X2[(z << 8) + col];
                    v1 += X2[(z << 8) + col + 1];
                    v0 = 0.5f * v0 * (1.f + erff(v0 * 0.70710678118654752f));
                    v1 = 0.5f * v1 * (1.f + erff(v1 * 0.70710678118654752f));
                } else if (MODE == 3) {
                    v0 += X2[(z << 10) + col];
                    v1 += X2[(z << 10) + col + 1];
                }
                *(float2*)(orow + col) = make_float2(v0, v1);
            }
        }
    }
}

// ---------------- launch ------------------------------------------------------
static const int GEMM_SMEM = 98304;  // 2 * (4096 + 8192) floats

extern "C" void kernel_launch(void* const* d_in, const int* in_sizes, int n_in,
                              void* d_out, int out_size) {
    const float* x     = (const float*)d_in[0];
    const float* gamma = (const float*)d_in[1];
    const float* beta  = (const float*)d_in[2];
    const float* mu    = (const float*)d_in[3];
    const float* scale = (const float*)d_in[4];
    const float* w1    = (const float*)d_in[5];
    const float* b1    = (const float*)d_in[6];
    const float* w2    = (const float*)d_in[7];
    const float* b2    = (const float*)d_in[8];
    float* out = (float*)d_out;

    static int attr_done = 0;
    if (!attr_done) {
        cudaFuncSetAttribute(gemm_mma<0>, cudaFuncAttributeMaxDynamicSharedMemorySize, GEMM_SMEM);
        cudaFuncSetAttribute(gemm_mma<1>, cudaFuncAttributeMaxDynamicSharedMemorySize, GEMM_SMEM);
        cudaFuncSetAttribute(gemm_mma<2>, cudaFuncAttributeMaxDynamicSharedMemorySize, GEMM_SMEM);
        cudaFuncSetAttribute(gemm_mma<3>, cudaFuncAttributeMaxDynamicSharedMemorySize, GEMM_SMEM);
        cudaFuncSetAttribute(gemm_mma<4>, cudaFuncAttributeMaxDynamicSharedMemorySize, GEMM_SMEM);
        attr_done = 1;
    }

    ln_kernel<<<NTOK, 256>>>(x, gamma, beta);
    munorm_kernel<<<CC, 256>>>(mu);
    gemm_mma<0><<<dim3(1, 128, 1), 256, GEMM_SMEM>>>(mu, nullptr, nullptr, scale);
    combine_kernel<<<NTOK / 8, dim3(32, 8)>>>();
    dispatch_kernel<<<dim3(8, 64), 256>>>();
    gemm_mma<1><<<dim3(4, 2, 64), 256, GEMM_SMEM>>>(nullptr, nullptr, nullptr, nullptr);
    gemm_mma<2><<<dim3(1, 8, 16), 256, GEMM_SMEM>>>(w1, b1, nullptr, nullptr);
    gemm_mma<3><<<dim3(4, 8, 16), 256, GEMM_SMEM>>>(w2, b2, nullptr, nullptr);
    gemm_mma<4><<<dim3(4, 2, 64), 256, GEMM_SMEM>>>(nullptr, nullptr, out, nullptr);
}

// round 5
// speedup vs baseline: 3.2285x; 1.1141x over previous
#include <cuda_runtime.h>
#include <math.h>
#include <stdint.h>

#define NTOK 16384
#define DD   1024
#define CC   256
#define BATCH 64
#define NSEQ 256
#define NEXP 16
#define HH   256

// ---------------- scratch ----------------------------------------------------
__device__ float g_xn[NTOK * DD];              // tf32-rounded LN output
__device__ float g_rnorm[NTOK];
__device__ float g_cinv[CC];
__device__ float g_logits[NTOK * CC];
__device__ float g_dispT[BATCH * CC * NSEQ];   // tf32-rounded, [b][c][n]
__device__ float g_combine[NTOK * CC];         // tf32-rounded
__device__ float g_slot[BATCH * CC * DD];      // tf32-rounded slot_in/out
__device__ float g_h[NEXP * 1024 * HH];        // tf32-rounded hidden
__device__ float g_mur[DD * CC];               // tf32-rounded weights
__device__ float g_w1r[NEXP * DD * HH];
__device__ float g_w2r[NEXP * HH * DD];

// ---------------- helpers ----------------------------------------------------
__device__ __forceinline__ float tf32r(float x) {
    asm("cvt.rna.tf32.f32 %0, %0;" : "+f"(x));
    return x;
}
__device__ __forceinline__ uint32_t smem_u32(const void* p) {
    uint32_t a;
    asm("{ .reg .u64 t; cvta.to.shared.u64 t, %1; cvt.u32.u64 %0, t; }" : "=r"(a) : "l"(p));
    return a;
}
__device__ __forceinline__ void cpa16(uint32_t dst, const void* src) {
    asm volatile("cp.async.cg.shared.global [%0], [%1], 16;" :: "r"(dst), "l"(src));
}
#define CP_COMMIT() asm volatile("cp.async.commit_group;" ::: "memory")
#define CP_WAIT1()  asm volatile("cp.async.wait_group 1;" ::: "memory")

__device__ __forceinline__ void mma_tf32(float* d, const uint32_t* a, const uint32_t* b) {
    asm volatile(
        "mma.sync.aligned.m16n8k8.row.col.f32.tf32.tf32.f32 "
        "{%0,%1,%2,%3}, {%4,%5,%6,%7}, {%8,%9}, {%0,%1,%2,%3};"
        : "+f"(d[0]), "+f"(d[1]), "+f"(d[2]), "+f"(d[3])
        : "r"(a[0]), "r"(a[1]), "r"(a[2]), "r"(a[3]), "r"(b[0]), "r"(b[1]));
}

// ---------------- weight pre-rounding ----------------------------------------
__global__ void round_copy(const float* __restrict__ src, float* __restrict__ dst) {
    int i = blockIdx.x * 256 + threadIdx.x;
    float4 v = ((const float4*)src)[i];
    v.x = tf32r(v.x); v.y = tf32r(v.y); v.z = tf32r(v.z); v.w = tf32r(v.w);
    ((float4*)dst)[i] = v;
}

// ---------------- LayerNorm + token L2 norm (writes tf32-rounded) -------------
__global__ void ln_kernel(const float* __restrict__ x,
                          const float* __restrict__ gamma,
                          const float* __restrict__ beta) {
    int t = blockIdx.x, tid = threadIdx.x;
    const float* xr = x + (size_t)t * DD;
    float* yr = g_xn + (size_t)t * DD;
    float lv[4], s = 0.f, ss = 0.f;
#pragma unroll
    for (int j = 0; j < 4; j++) {
        float a = xr[tid + 256 * j];
        lv[j] = a; s += a; ss += a * a;
    }
    __shared__ float r1[256], r2[256];
    r1[tid] = s; r2[tid] = ss; __syncthreads();
    for (int o = 128; o > 0; o >>= 1) {
        if (tid < o) { r1[tid] += r1[tid + o]; r2[tid] += r2[tid + o]; }
        __syncthreads();
    }
    float mean = r1[0] * (1.f / DD);
    float var  = r2[0] * (1.f / DD) - mean * mean;
    float rstd = rsqrtf(var + 1e-5f);
    float s2 = 0.f;
#pragma unroll
    for (int j = 0; j < 4; j++) {
        int i = tid + 256 * j;
        float y = tf32r((lv[j] - mean) * rstd * gamma[i] + beta[i]);
        yr[i] = y; s2 += y * y;
    }
    __syncthreads();
    r1[tid] = s2; __syncthreads();
    for (int o = 128; o > 0; o >>= 1) {
        if (tid < o) r1[tid] += r1[tid + o];
        __syncthreads();
    }
    if (tid == 0) g_rnorm[t] = 1.f / fmaxf(sqrtf(r1[0]), 1e-12f);
}

__global__ void munorm_kernel(const float* __restrict__ mu) {
    int c = blockIdx.x, tid = threadIdx.x;
    float s = 0.f;
    for (int d = tid; d < DD; d += 256) {
        float a = mu[(size_t)d * CC + c];
        s += a * a;
    }
    __shared__ float r[256];
    r[tid] = s; __syncthreads();
    for (int o = 128; o > 0; o >>= 1) {
        if (tid < o) r[tid] += r[tid + o];
        __syncthreads();
    }
    if (tid == 0) g_cinv[c] = 1.f / fmaxf(sqrtf(r[0]), 1e-12f);
}

// ---------------- combine softmax (writes tf32-rounded) -----------------------
__global__ void combine_kernel() {
    int row = blockIdx.x * 8 + threadIdx.y;
    int lane = threadIdx.x;
    const float* lr = g_logits + (size_t)row * CC;
    float v[8]; float mx = -1e30f;
#pragma unroll
    for (int j = 0; j < 8; j++) { v[j] = lr[lane + 32 * j]; mx = fmaxf(mx, v[j]); }
    for (int o = 16; o > 0; o >>= 1) mx = fmaxf(mx, __shfl_xor_sync(0xffffffffu, mx, o));
    float s = 0.f;
#pragma unroll
    for (int j = 0; j < 8; j++) { v[j] = __expf(v[j] - mx); s += v[j]; }
    for (int o = 16; o > 0; o >>= 1) s += __shfl_xor_sync(0xffffffffu, s, o);
    float inv = 1.f / s;
    float* cr = g_combine + (size_t)row * CC;
#pragma unroll
    for (int j = 0; j < 8; j++) cr[lane + 32 * j] = tf32r(v[j] * inv);
}

// ---------------- dispatch softmax over tokens; transposed tf32 output --------
__global__ void dispatch_kernel() {
    int b = blockIdx.y, c0 = blockIdx.x * 32, tid = threadIdx.x;
    int c = tid & 31, nb = tid >> 5;
    __shared__ float tile[256][33];
    __shared__ float pred[8][32];
    __shared__ float colv[32];

    const size_t base = ((size_t)b * NSEQ) * CC + c0;
#pragma unroll
    for (int it = 0; it < 32; it++) {
        int n = nb + 8 * it;
        tile[n][c] = g_logits[base + (size_t)n * CC + c];
    }
    __syncthreads();
    float mx = -1e30f;
#pragma unroll
    for (int j = 0; j < 32; j++) mx = fmaxf(mx, tile[nb * 32 + j][c]);
    pred[nb][c] = mx; __syncthreads();
    if (nb == 0) {
        float m = pred[0][c];
#pragma unroll
        for (int j = 1; j < 8; j++) m = fmaxf(m, pred[j][c]);
        colv[c] = m;
    }
    __syncthreads();
    float cm = colv[c];
    float s = 0.f;
#pragma unroll
    for (int j = 0; j < 32; j++) {
        float e = __expf(tile[nb * 32 + j][c] - cm);
        tile[nb * 32 + j][c] = e; s += e;
    }
    pred[nb][c] = s; __syncthreads();
    if (nb == 0) {
        float t = 0.f;
#pragma unroll
        for (int j = 0; j < 8; j++) t += pred[j][c];
        colv[c] = 1.f / t;
    }
    __syncthreads();
    int lane2 = tid & 31, cg = tid >> 5;
#pragma unroll
    for (int cc2 = 0; cc2 < 4; cc2++) {
        int cl = cg + 8 * cc2;
        float inv = colv[cl];
        size_t ob = ((size_t)b * CC + c0 + cl) * NSEQ;
#pragma unroll
        for (int itn = 0; itn < 8; itn++) {
            int n = lane2 + 32 * itn;
            g_dispT[ob + n] = tf32r(tile[n][cl] * inv);
        }
    }
}

// ---------------- tf32 mma.sync GEMM, cp.async 3-stage, CTA 128x256 -----------
// A smem: [128][36] words (pad 32->36), B smem: [32][264] words (pad 256->264)
#define STG_W 13056          // words per stage: 128*36 + 32*264
#define A_W   4608

template <int MODE>
__global__ void __launch_bounds__(256) gemm_cp(const float* __restrict__ X2,
                                               float* __restrict__ Cout,
                                               const float* __restrict__ sp) {
    constexpr int Kx  = (MODE == 0 || MODE == 2) ? 1024 : 256;
    constexpr int ldb = (MODE == 0 || MODE == 2) ? 256 : 1024;
    constexpr int lda = (MODE == 0 || MODE == 2) ? 1024 : 256;
    constexpr int NC  = Kx / 32;

    extern __shared__ float sm[];
    const uint32_t sb = smem_u32(sm);
    const int tid = threadIdx.x, wid = tid >> 5, lane = tid & 31;
    const int warp_m = wid & 1, warp_n = wid >> 1;
    const int r = lane >> 2, t = lane & 3;
    const int z = blockIdx.z, m0 = blockIdx.y * 128, n0 = blockIdx.x * 256;

    const float* Abase;
    const float* Bbase;
    if (MODE == 0)      { Abase = g_xn + (size_t)m0 * 1024;                         Bbase = g_mur; }
    else if (MODE == 1) { Abase = g_dispT + ((size_t)z << 16) + (size_t)m0 * 256;   Bbase = g_xn + ((size_t)z << 18); }
    else if (MODE == 2) { Abase = g_slot;                                           Bbase = g_w1r + ((size_t)z << 18); }
    else if (MODE == 3) { Abase = g_h + ((size_t)z << 18) + (size_t)m0 * 256;       Bbase = g_w2r + ((size_t)z << 18); }
    else                { Abase = g_combine + ((size_t)z << 16) + (size_t)m0 * 256; Bbase = g_slot + ((size_t)z << 18); }

    // staging geometry: A = 4 cp.async/thread, B = 8 cp.async/thread (32 k-rows)
    const int kq = tid & 7;          // A: float4 index along k
    const int nq = tid & 63;         // B: float4 index along n
    const float* arow_i[4];
#pragma unroll
    for (int i = 0; i < 4; i++) {
        int m = (tid >> 3) + 32 * i;
        if (MODE == 2) {
            int g = m0 + m;
            arow_i[i] = g_slot + (size_t)(((g >> 4) << 8) + (z << 4) + (g & 15)) * 1024;
        } else {
            arow_i[i] = Abase + (size_t)m * lda;
        }
    }
    const float* bcol = Bbase + n0 + nq * 4;
    const uint32_t a_dst0 = sb + ((tid >> 3) * 36 + kq * 4) * 4;
    const uint32_t b_dst0 = sb + (A_W + (tid >> 6) * 264 + nq * 4) * 4;

    float acc[4][8][4];
#pragma unroll
    for (int mt = 0; mt < 4; mt++)
#pragma unroll
        for (int nt = 0; nt < 8; nt++)
#pragma unroll
            for (int q = 0; q < 4; q++) acc[mt][nt][q] = 0.f;

    // prologue: stages 0, 1
#pragma unroll
    for (int st = 0; st < 2; st++) {
        const int k0 = st * 32;
#pragma unroll
        for (int i = 0; i < 4; i++)
            cpa16(a_dst0 + st * (STG_W * 4) + i * (32 * 36 * 4), arow_i[i] + k0 + kq * 4);
#pragma unroll
        for (int i = 0; i < 8; i++)
            cpa16(b_dst0 + st * (STG_W * 4) + i * (4 * 264 * 4), bcol + (size_t)(k0 + (tid >> 6) + 4 * i) * ldb);
        CP_COMMIT();
    }

    int st = 0;
#pragma unroll 1
    for (int s = 0; s < NC; s++) {
        CP_WAIT1();
        __syncthreads();

        // compute stage st
        {
            const uint32_t* As = (const uint32_t*)(sm + st * STG_W);
            const uint32_t* Bs = As + A_W;
            const uint32_t* Aw = As + (warp_m * 64 + r) * 36 + t;
            const uint32_t* Bw = Bs + t * 264 + warp_n * 64 + r;
#pragma unroll
            for (int k8 = 0; k8 < 4; k8++) {
                uint32_t a[4][4], b[8][2];
#pragma unroll
                for (int mt = 0; mt < 4; mt++) {
                    const uint32_t* ap = Aw + mt * (16 * 36) + k8 * 8;
                    a[mt][0] = ap[0];
                    a[mt][1] = ap[8 * 36];
                    a[mt][2] = ap[4];
                    a[mt][3] = ap[8 * 36 + 4];
                }
#pragma unroll
                for (int nt = 0; nt < 8; nt++) {
                    const uint32_t* bp = Bw + k8 * (8 * 264) + nt * 8;
                    b[nt][0] = bp[0];
                    b[nt][1] = bp[4 * 264];
                }
#pragma unroll
                for (int mt = 0; mt < 4; mt++)
#pragma unroll
                    for (int nt = 0; nt < 8; nt++)
                        mma_tf32(acc[mt][nt], a[mt], b[nt]);
            }
        }

        // issue stage s+2 (after compute; sync at top protects WAR)
        if (s + 2 < NC) {
            const int ld = (s + 2) % 3;
            const int k0 = (s + 2) * 32;
#pragma unroll
            for (int i = 0; i < 4; i++)
                cpa16(a_dst0 + ld * (STG_W * 4) + i * (32 * 36 * 4), arow_i[i] + k0 + kq * 4);
#pragma unroll
            for (int i = 0; i < 8; i++)
                cpa16(b_dst0 + ld * (STG_W * 4) + i * (4 * 264 * 4), bcol + (size_t)(k0 + (tid >> 6) + 4 * i) * ldb);
        }
        CP_COMMIT();
        st = (st + 1 == 3) ? 0 : st + 1;
    }

    // ---- epilogue
    float spv = (MODE == 0) ? sp[0] : 0.f;
#pragma unroll
    for (int mt = 0; mt < 4; mt++) {
        int row = m0 + warp_m * 64 + mt * 16 + r;
#pragma unroll
        for (int half = 0; half < 2; half++) {
            int rw = row + half * 8;
            float rs0 = 0.f;
            if (MODE == 0) rs0 = spv * g_rnorm[rw];
            float* orow;
            if (MODE == 0)      orow = g_logits + (size_t)rw * 256;
            else if (MODE == 1) orow = g_slot + (((size_t)z << 8) + rw) * 1024;
            else if (MODE == 2) orow = g_h + (((size_t)z << 10) + rw) * 256;
            else if (MODE == 3) {
                int rr = ((rw >> 4) << 8) + (z << 4) + (rw & 15);
                orow = g_slot + (size_t)rr * 1024;
            } else              orow = Cout + (((size_t)z << 8) + rw) * 1024;
#pragma unroll
            for (int nt = 0; nt < 8; nt++) {
                int col = n0 + warp_n * 64 + nt * 8 + 2 * t;
                float v0 = acc[mt][nt][half * 2 + 0];
                float v1 = acc[mt][nt][half * 2 + 1];
                if (MODE == 0) {
                    v0 *= rs0 * g_cinv[col];
                    v1 *= rs0 * g_cinv[col + 1];
                } else if (MODE == 1) {
                    v0 = tf32r(v0); v1 = tf32r(v1);
                } else if (MODE == 2) {
                    v0 += X2[(z << 8) + col];
                    v1 += X2[(z << 8) + col + 1];
                    v0 = tf32r(0.5f * v0 * (1.f + erff(v0 * 0.70710678118654752f)));
                    v1 = tf32r(0.5f * v1 * (1.f + erff(v1 * 0.70710678118654752f)));
                } else if (MODE == 3) {
                    v0 = tf32r(v0 + X2[(z << 10) + col]);
                    v1 = tf32r(v1 + X2[(z << 10) + col + 1]);
                }
                *(float2*)(orow + col) = make_float2(v0, v1);
            }
        }
    }
}

// ---------------- launch ------------------------------------------------------
static const int GEMM_SMEM = 3 * STG_W * 4;   // 156,672 bytes

extern "C" void kernel_launch(void* const* d_in, const int* in_sizes, int n_in,
                              void* d_out, int out_size) {
    const float* x     = (const float*)d_in[0];
    const float* gamma = (const float*)d_in[1];
    const float* beta  = (const float*)d_in[2];
    const float* mu    = (const float*)d_in[3];
    const float* scale = (const float*)d_in[4];
    const float* w1    = (const float*)d_in[5];
    const float* b1    = (const float*)d_in[6];
    const float* w2    = (const float*)d_in[7];
    const float* b2    = (const float*)d_in[8];
    float* out = (float*)d_out;

    static int attr_done = 0;
    if (!attr_done) {
        cudaFuncSetAttribute(gemm_cp<0>, cudaFuncAttributeMaxDynamicSharedMemorySize, GEMM_SMEM);
        cudaFuncSetAttribute(gemm_cp<1>, cudaFuncAttributeMaxDynamicSharedMemorySize, GEMM_SMEM);
        cudaFuncSetAttribute(gemm_cp<2>, cudaFuncAttributeMaxDynamicSharedMemorySize, GEMM_SMEM);
        cudaFuncSetAttribute(gemm_cp<3>, cudaFuncAttributeMaxDynamicSharedMemorySize, GEMM_SMEM);
        cudaFuncSetAttribute(gemm_cp<4>, cudaFuncAttributeMaxDynamicSharedMemorySize, GEMM_SMEM);
        attr_done = 1;
    }

    float* g_mur_p; cudaGetSymbolAddress((void**)&g_mur_p, g_mur);
    float* g_w1r_p; cudaGetSymbolAddress((void**)&g_w1r_p, g_w1r);
    float* g_w2r_p; cudaGetSymbolAddress((void**)&g_w2r_p, g_w2r);

    ln_kernel<<<NTOK, 256>>>(x, gamma, beta);
    munorm_kernel<<<CC, 256>>>(mu);
    round_copy<<<DD * CC / 1024, 256>>>(mu, g_mur_p);
    round_copy<<<NEXP * DD * HH / 1024, 256>>>(w1, g_w1r_p);
    round_copy<<<NEXP * HH * DD / 1024, 256>>>(w2, g_w2r_p);
    gemm_cp<0><<<dim3(1, 128, 1), 256, GEMM_SMEM>>>(nullptr, nullptr, scale);
    combine_kernel<<<NTOK / 8, dim3(32, 8)>>>();
    dispatch_kernel<<<dim3(8, 64), 256>>>();
    gemm_cp<1><<<dim3(4, 2, 64), 256, GEMM_SMEM>>>(nullptr, nullptr, nullptr);
    gemm_cp<2><<<dim3(1, 8, 16), 256, GEMM_SMEM>>>(b1, nullptr, nullptr);
    gemm_cp<3><<<dim3(4, 8, 16), 256, GEMM_SMEM>>>(b2, nullptr, nullptr);
    gemm_cp<4><<<dim3(4, 2, 64), 256, GEMM_SMEM>>>(nullptr, out, nullptr);
}

// round 6
// speedup vs baseline: 4.3675x; 1.3528x over previous
#include <cuda_runtime.h>
#include <cuda_fp16.h>
#include <math.h>
#include <stdint.h>

#define NTOK 16384
#define DD   1024
#define CC   256
#define BATCH 64
#define NSEQ 256
#define NEXP 16
#define HH   256

// ---------------- scratch ----------------------------------------------------
__device__ __half g_xn_h[NTOK * DD];            // LN output, fp16
__device__ float  g_rnorm[NTOK];
__device__ float  g_cinv[CC];
__device__ float  g_logits[NTOK * CC];          // fp32 (softmax input)
__device__ __half g_dispT_h[BATCH * CC * NSEQ]; // [b][c][n]
__device__ __half g_comb_h[NTOK * CC];
__device__ __half g_slot_h[BATCH * CC * DD];    // slot_in then slot_out
__device__ __half g_hh[NEXP * 1024 * HH];
__device__ __half g_mur_h[DD * CC];
__device__ __half g_w1_h[NEXP * DD * HH];
__device__ __half g_w2_h[NEXP * HH * DD];

// ---------------- helpers ----------------------------------------------------
__device__ __forceinline__ uint32_t smem_u32(const void* p) {
    uint32_t a;
    asm("{ .reg .u64 t; cvta.to.shared.u64 t, %1; cvt.u32.u64 %0, t; }" : "=r"(a) : "l"(p));
    return a;
}
__device__ __forceinline__ void cpa16(uint32_t dst, const void* src) {
    asm volatile("cp.async.cg.shared.global [%0], [%1], 16;" :: "r"(dst), "l"(src));
}
#define CP_COMMIT() asm volatile("cp.async.commit_group;" ::: "memory")
#define CP_WAIT1()  asm volatile("cp.async.wait_group 1;" ::: "memory")

__device__ __forceinline__ void ldsm4(uint32_t* r, uint32_t addr) {
    asm volatile("ldmatrix.sync.aligned.m8n8.x4.shared.b16 {%0,%1,%2,%3}, [%4];"
                 : "=r"(r[0]), "=r"(r[1]), "=r"(r[2]), "=r"(r[3]) : "r"(addr));
}
__device__ __forceinline__ void ldsm4t(uint32_t* r, uint32_t addr) {
    asm volatile("ldmatrix.sync.aligned.m8n8.x4.trans.shared.b16 {%0,%1,%2,%3}, [%4];"
                 : "=r"(r[0]), "=r"(r[1]), "=r"(r[2]), "=r"(r[3]) : "r"(addr));
}
__device__ __forceinline__ void mma_f16(float* d, const uint32_t* a, const uint32_t* b) {
    asm volatile(
        "mma.sync.aligned.m16n8k16.row.col.f32.f16.f16.f32 "
        "{%0,%1,%2,%3}, {%4,%5,%6,%7}, {%8,%9}, {%0,%1,%2,%3};"
        : "+f"(d[0]), "+f"(d[1]), "+f"(d[2]), "+f"(d[3])
        : "r"(a[0]), "r"(a[1]), "r"(a[2]), "r"(a[3]), "r"(b[0]), "r"(b[1]));
}

// ---------------- fp32 -> fp16 conversion ------------------------------------
__global__ void half_copy(const float* __restrict__ src, __half* __restrict__ dst) {
    int i = blockIdx.x * 256 + threadIdx.x;
    float4 v = ((const float4*)src)[i];
    ((__half2*)dst)[2 * i]     = __floats2half2_rn(v.x, v.y);
    ((__half2*)dst)[2 * i + 1] = __floats2half2_rn(v.z, v.w);
}

// ---------------- LayerNorm + token L2 norm (fp16 output) ---------------------
__global__ void ln_kernel(const float* __restrict__ x,
                          const float* __restrict__ gamma,
                          const float* __restrict__ beta) {
    int t = blockIdx.x, tid = threadIdx.x;
    const float* xr = x + (size_t)t * DD;
    __half* yr = g_xn_h + (size_t)t * DD;
    float lv[4], s = 0.f, ss = 0.f;
#pragma unroll
    for (int j = 0; j < 4; j++) {
        float a = xr[tid + 256 * j];
        lv[j] = a; s += a; ss += a * a;
    }
    __shared__ float r1[256], r2[256];
    r1[tid] = s; r2[tid] = ss; __syncthreads();
    for (int o = 128; o > 0; o >>= 1) {
        if (tid < o) { r1[tid] += r1[tid + o]; r2[tid] += r2[tid + o]; }
        __syncthreads();
    }
    float mean = r1[0] * (1.f / DD);
    float var  = r2[0] * (1.f / DD) - mean * mean;
    float rstd = rsqrtf(var + 1e-5f);
    float s2 = 0.f;
#pragma unroll
    for (int j = 0; j < 4; j++) {
        int i = tid + 256 * j;
        __half yh = __float2half_rn((lv[j] - mean) * rstd * gamma[i] + beta[i]);
        float yq = __half2float(yh);
        yr[i] = yh; s2 += yq * yq;
    }
    __syncthreads();
    r1[tid] = s2; __syncthreads();
    for (int o = 128; o > 0; o >>= 1) {
        if (tid < o) r1[tid] += r1[tid + o];
        __syncthreads();
    }
    if (tid == 0) g_rnorm[t] = 1.f / fmaxf(sqrtf(r1[0]), 1e-12f);
}

__global__ void munorm_kernel(const float* __restrict__ mu) {
    int c = blockIdx.x, tid = threadIdx.x;
    float s = 0.f;
    for (int d = tid; d < DD; d += 256) {
        float a = mu[(size_t)d * CC + c];
        s += a * a;
    }
    __shared__ float r[256];
    r[tid] = s; __syncthreads();
    for (int o = 128; o > 0; o >>= 1) {
        if (tid < o) r[tid] += r[tid + o];
        __syncthreads();
    }
    if (tid == 0) g_cinv[c] = 1.f / fmaxf(sqrtf(r[0]), 1e-12f);
}

// ---------------- combine softmax (fp16 output) --------------------------------
__global__ void combine_kernel() {
    int row = blockIdx.x * 8 + threadIdx.y;
    int lane = threadIdx.x;
    const float* lr = g_logits + (size_t)row * CC;
    float v[8]; float mx = -1e30f;
#pragma unroll
    for (int j = 0; j < 8; j++) { v[j] = lr[lane + 32 * j]; mx = fmaxf(mx, v[j]); }
    for (int o = 16; o > 0; o >>= 1) mx = fmaxf(mx, __shfl_xor_sync(0xffffffffu, mx, o));
    float s = 0.f;
#pragma unroll
    for (int j = 0; j < 8; j++) { v[j] = __expf(v[j] - mx); s += v[j]; }
    for (int o = 16; o > 0; o >>= 1) s += __shfl_xor_sync(0xffffffffu, s, o);
    float inv = 1.f / s;
    __half* cr = g_comb_h + (size_t)row * CC;
#pragma unroll
    for (int j = 0; j < 8; j++) cr[lane + 32 * j] = __float2half_rn(v[j] * inv);
}

// ---------------- dispatch softmax; transposed fp16 output ---------------------
__global__ void dispatch_kernel() {
    int b = blockIdx.y, c0 = blockIdx.x * 32, tid = threadIdx.x;
    int c = tid & 31, nb = tid >> 5;
    __shared__ float tile[256][33];
    __shared__ float pred[8][32];
    __shared__ float colv[32];

    const size_t base = ((size_t)b * NSEQ) * CC + c0;
#pragma unroll
    for (int it = 0; it < 32; it++) {
        int n = nb + 8 * it;
        tile[n][c] = g_logits[base + (size_t)n * CC + c];
    }
    __syncthreads();
    float mx = -1e30f;
#pragma unroll
    for (int j = 0; j < 32; j++) mx = fmaxf(mx, tile[nb * 32 + j][c]);
    pred[nb][c] = mx; __syncthreads();
    if (nb == 0) {
        float m = pred[0][c];
#pragma unroll
        for (int j = 1; j < 8; j++) m = fmaxf(m, pred[j][c]);
        colv[c] = m;
    }
    __syncthreads();
    float cm = colv[c];
    float s = 0.f;
#pragma unroll
    for (int j = 0; j < 32; j++) {
        float e = __expf(tile[nb * 32 + j][c] - cm);
        tile[nb * 32 + j][c] = e; s += e;
    }
    pred[nb][c] = s; __syncthreads();
    if (nb == 0) {
        float t = 0.f;
#pragma unroll
        for (int j = 0; j < 8; j++) t += pred[j][c];
        colv[c] = 1.f / t;
    }
    __syncthreads();
    int lane2 = tid & 31, cg = tid >> 5;
#pragma unroll
    for (int cc2 = 0; cc2 < 4; cc2++) {
        int cl = cg + 8 * cc2;
        float inv = colv[cl];
        size_t ob = ((size_t)b * CC + c0 + cl) * NSEQ;
#pragma unroll
        for (int itn = 0; itn < 8; itn++) {
            int n = lane2 + 32 * itn;
            g_dispT_h[ob + n] = __float2half_rn(tile[n][cl] * inv);
        }
    }
}

// ---------------- fp16 mma.sync GEMM, cp.async 3-stage, CTA 128x256 ------------
// A smem: 128 rows x 40 halfs (80 B stride, data 32); B smem: 32 k x 264 halfs.
// MODE 0: logits  = xn @ mur            + cosine scale   (K=1024,N=256) fp32 out
// MODE 1: slot_in = dispT[b] @ xn[b]                     (K=256, N=1024) fp16 out
// MODE 2: h       = gather(slot) @ w1   + b1 + GELU      (K=1024,N=256) fp16 out
// MODE 3: slot_out= h[e] @ w2[e]        + b2 + scatter   (K=256, N=1024) fp16 out
// MODE 4: out[b]  = comb[b] @ slot                       (K=256, N=1024) fp32 out
#define STG_B 27136          // bytes per stage: 128*80 + 32*528
#define B_OFF 10240          // byte offset of B region within stage

template <int MODE>
__global__ void __launch_bounds__(256) gemm_h(const float* __restrict__ X2,
                                              float* __restrict__ Cout,
                                              const float* __restrict__ sp) {
    constexpr int Kx  = (MODE == 0 || MODE == 2) ? 1024 : 256;
    constexpr int ldb = (MODE == 0 || MODE == 2) ? 256 : 1024;
    constexpr int lda = (MODE == 0 || MODE == 2) ? 1024 : 256;
    constexpr int NC  = Kx / 32;

    extern __shared__ __half sm[];
    const uint32_t sb = smem_u32(sm);
    const int tid = threadIdx.x, wid = tid >> 5, lane = tid & 31;
    const int warp_m = wid & 1, warp_n = wid >> 1;
    const int r = lane >> 2, t = lane & 3;
    const int z = blockIdx.z, m0 = blockIdx.y * 128, n0 = blockIdx.x * 256;

    const __half* Abase;
    const __half* Bbase;
    if (MODE == 0)      { Abase = g_xn_h + (size_t)m0 * 1024;                        Bbase = g_mur_h; }
    else if (MODE == 1) { Abase = g_dispT_h + ((size_t)z << 16) + (size_t)m0 * 256;  Bbase = g_xn_h + ((size_t)z << 18); }
    else if (MODE == 2) { Abase = g_slot_h;                                          Bbase = g_w1_h + ((size_t)z << 18); }
    else if (MODE == 3) { Abase = g_hh + ((size_t)z << 18) + (size_t)m0 * 256;       Bbase = g_w2_h + ((size_t)z << 18); }
    else                { Abase = g_comb_h + ((size_t)z << 16) + (size_t)m0 * 256;   Bbase = g_slot_h + ((size_t)z << 18); }

    // staging: A 2 cp/thread, B 4 cp/thread
    const int am  = tid >> 1;              // A row 0..127
    const int akh = (tid & 1) * 16;        // A k-half offset (halfs)
    const int bk  = tid >> 3;              // B k-row 0..31
    const int bn8 = (tid & 7) * 8;         // B n offset (halfs)
    const __half* arow;
    if (MODE == 2) {
        int g = m0 + am;
        arow = g_slot_h + (size_t)(((g >> 4) << 8) + (z << 4) + (g & 15)) * 1024;
    } else {
        arow = Abase + (size_t)am * lda;
    }
    const __half* brow = Bbase + n0 + bn8;
    const uint32_t a_dst0 = sb + am * 80 + akh * 2;
    const uint32_t b_dst0 = sb + B_OFF + bk * 528 + bn8 * 2;

    float acc[4][8][4];
#pragma unroll
    for (int mt = 0; mt < 4; mt++)
#pragma unroll
        for (int nt = 0; nt < 8; nt++)
#pragma unroll
            for (int q = 0; q < 4; q++) acc[mt][nt][q] = 0.f;

    // prologue: stages 0, 1
#pragma unroll
    for (int stg = 0; stg < 2; stg++) {
        const int k0 = stg * 32;
#pragma unroll
        for (int i = 0; i < 2; i++)
            cpa16(a_dst0 + stg * STG_B + i * 16, arow + k0 + akh + i * 8);
#pragma unroll
        for (int i = 0; i < 4; i++)
            cpa16(b_dst0 + stg * STG_B + i * 128, brow + (size_t)(k0 + bk) * ldb + i * 64);
        CP_COMMIT();
    }

    int st = 0;
#pragma unroll 1
    for (int s = 0; s < NC; s++) {
        CP_WAIT1();
        __syncthreads();

        // compute stage st
        {
            const uint32_t base = sb + st * STG_B;
            const uint32_t a_ld = base + (warp_m * 64 + (lane & 15)) * 80 + (lane >> 4) * 16;
            const uint32_t b_ld = base + B_OFF + (((lane >> 3) & 1) * 8 + (lane & 7)) * 528
                                  + (warp_n * 64 + (lane >> 4) * 8) * 2;
#pragma unroll
            for (int ks = 0; ks < 2; ks++) {
                uint32_t a[4][4], b[8][2];
#pragma unroll
                for (int mt = 0; mt < 4; mt++)
                    ldsm4(a[mt], a_ld + mt * (16 * 80) + ks * 32);
#pragma unroll
                for (int ntp = 0; ntp < 4; ntp++) {
                    uint32_t bb[4];
                    ldsm4t(bb, b_ld + ks * (16 * 528) + ntp * 32);
                    b[2 * ntp][0] = bb[0]; b[2 * ntp][1] = bb[1];
                    b[2 * ntp + 1][0] = bb[2]; b[2 * ntp + 1][1] = bb[3];
                }
#pragma unroll
                for (int mt = 0; mt < 4; mt++)
#pragma unroll
                    for (int nt = 0; nt < 8; nt++)
                        mma_f16(acc[mt][nt], a[mt], b[nt]);
            }
        }

        // issue stage s+2
        if (s + 2 < NC) {
            const int ld = (s + 2) % 3;
            const int k0 = (s + 2) * 32;
#pragma unroll
            for (int i = 0; i < 2; i++)
                cpa16(a_dst0 + ld * STG_B + i * 16, arow + k0 + akh + i * 8);
#pragma unroll
            for (int i = 0; i < 4; i++)
                cpa16(b_dst0 + ld * STG_B + i * 128, brow + (size_t)(k0 + bk) * ldb + i * 64);
        }
        CP_COMMIT();
        st = (st + 1 == 3) ? 0 : st + 1;
    }

    // ---- epilogue
    float spv = (MODE == 0) ? sp[0] : 0.f;
#pragma unroll
    for (int mt = 0; mt < 4; mt++) {
        int row = m0 + warp_m * 64 + mt * 16 + r;
#pragma unroll
        for (int hf = 0; hf < 2; hf++) {
            int rw = row + hf * 8;
            float rs0 = 0.f;
            if (MODE == 0) rs0 = spv * g_rnorm[rw];
#pragma unroll
            for (int nt = 0; nt < 8; nt++) {
                int col = n0 + warp_n * 64 + nt * 8 + 2 * t;
                float v0 = acc[mt][nt][hf * 2 + 0];
                float v1 = acc[mt][nt][hf * 2 + 1];
                if (MODE == 0) {
                    v0 *= rs0 * g_cinv[col];
                    v1 *= rs0 * g_cinv[col + 1];
                    *(float2*)(g_logits + (size_t)rw * 256 + col) = make_float2(v0, v1);
                } else if (MODE == 1) {
                    __half* orow = g_slot_h + (((size_t)z << 8) + rw) * 1024;
                    *(__half2*)(orow + col) = __floats2half2_rn(v0, v1);
                } else if (MODE == 2) {
                    v0 += X2[(z << 8) + col];
                    v1 += X2[(z << 8) + col + 1];
                    v0 = 0.5f * v0 * (1.f + erff(v0 * 0.70710678118654752f));
                    v1 = 0.5f * v1 * (1.f + erff(v1 * 0.70710678118654752f));
                    __half* orow = g_hh + (((size_t)z << 10) + rw) * 256;
                    *(__half2*)(orow + col) = __floats2half2_rn(v0, v1);
                } else if (MODE == 3) {
                    v0 += X2[(z << 10) + col];
                    v1 += X2[(z << 10) + col + 1];
                    int rr = ((rw >> 4) << 8) + (z << 4) + (rw & 15);
                    __half* orow = g_slot_h + (size_t)rr * 1024;
                    *(__half2*)(orow + col) = __floats2half2_rn(v0, v1);
                } else {
                    *(float2*)(Cout + (((size_t)z << 8) + rw) * 1024 + col) = make_float2(v0, v1);
                }
            }
        }
    }
}

// ---------------- launch -------------------------------------------------------
static const int GEMM_SMEM = 3 * STG_B;   // 81,408 bytes

extern "C" void kernel_launch(void* const* d_in, const int* in_sizes, int n_in,
                              void* d_out, int out_size) {
    const float* x     = (const float*)d_in[0];
    const float* gamma = (const float*)d_in[1];
    const float* beta  = (const float*)d_in[2];
    const float* mu    = (const float*)d_in[3];
    const float* scale = (const float*)d_in[4];
    const float* w1    = (const float*)d_in[5];
    const float* b1    = (const float*)d_in[6];
    const float* w2    = (const float*)d_in[7];
    const float* b2    = (const float*)d_in[8];
    float* out = (float*)d_out;

    static int attr_done = 0;
    if (!attr_done) {
        cudaFuncSetAttribute(gemm_h<0>, cudaFuncAttributeMaxDynamicSharedMemorySize, GEMM_SMEM);
        cudaFuncSetAttribute(gemm_h<1>, cudaFuncAttributeMaxDynamicSharedMemorySize, GEMM_SMEM);
        cudaFuncSetAttribute(gemm_h<2>, cudaFuncAttributeMaxDynamicSharedMemorySize, GEMM_SMEM);
        cudaFuncSetAttribute(gemm_h<3>, cudaFuncAttributeMaxDynamicSharedMemorySize, GEMM_SMEM);
        cudaFuncSetAttribute(gemm_h<4>, cudaFuncAttributeMaxDynamicSharedMemorySize, GEMM_SMEM);
        attr_done = 1;
    }

    __half* mur_p; cudaGetSymbolAddress((void**)&mur_p, g_mur_h);
    __half* w1_p;  cudaGetSymbolAddress((void**)&w1_p,  g_w1_h);
    __half* w2_p;  cudaGetSymbolAddress((void**)&w2_p,  g_w2_h);

    ln_kernel<<<NTOK, 256>>>(x, gamma, beta);
    munorm_kernel<<<CC, 256>>>(mu);
    half_copy<<<DD * CC / 1024, 256>>>(mu, mur_p);
    half_copy<<<NEXP * DD * HH / 1024, 256>>>(w1, w1_p);
    half_copy<<<NEXP * HH * DD / 1024, 256>>>(w2, w2_p);
    gemm_h<0><<<dim3(1, 128, 1), 256, GEMM_SMEM>>>(nullptr, nullptr, scale);
    combine_kernel<<<NTOK / 8, dim3(32, 8)>>>();
    dispatch_kernel<<<dim3(8, 64), 256>>>();
    gemm_h<1><<<dim3(4, 2, 64), 256, GEMM_SMEM>>>(nullptr, nullptr, nullptr);
    gemm_h<2><<<dim3(1, 8, 16), 256, GEMM_SMEM>>>(b1, nullptr, nullptr);
    gemm_h<3><<<dim3(4, 8, 16), 256, GEMM_SMEM>>>(b2, nullptr, nullptr);
    gemm_h<4><<<dim3(4, 2, 64), 256, GEMM_SMEM>>>(nullptr, out, nullptr);
}